// round 1
// baseline (speedup 1.0000x reference)
#include <cuda_runtime.h>
#include <cuda_bf16.h>

// Net_33294586479043: 2-layer GCN ending in log_softmax over axis=1 of a
// [N, 1] tensor. log_softmax on a size-1 axis is identically 0.0 (exactly,
// even in fp32: x - x - log(exp(0)) = -log(1) = 0). The entire graph
// convolution is dead code; the reference output is 100,000 exact zeros.
//
// Therefore: one kernel that zero-fills d_out. out_size = 100000 floats
// (400 KB), divisible by 4 -> vectorized float4 stores; tail loop guards
// the general case anyway.

__global__ void zero_out_kernel(float4* __restrict__ out4, int n4,
                                float* __restrict__ out_tail, int tail_start, int n) {
    int i = blockIdx.x * blockDim.x + threadIdx.x;
    const float4 z = make_float4(0.f, 0.f, 0.f, 0.f);
    // grid-stride over float4 body
    for (int idx = i; idx < n4; idx += gridDim.x * blockDim.x) {
        out4[idx] = z;
    }
    // tail (0..3 elements) handled by thread 0 of block 0
    if (i == 0) {
        for (int t = tail_start; t < n; ++t) out_tail[t] = 0.0f;
    }
}

extern "C" void kernel_launch(void* const* d_in, const int* in_sizes, int n_in,
                              void* d_out, int out_size) {
    (void)d_in; (void)in_sizes; (void)n_in;
    float* out = (float*)d_out;
    int n = out_size;          // 100000 expected
    int n4 = n / 4;            // 25000 float4 stores
    int tail_start = n4 * 4;

    int threads = 256;
    int blocks = (n4 + threads - 1) / threads;
    if (blocks < 1) blocks = 1;

    zero_out_kernel<<<blocks, threads>>>((float4*)out, n4, out, tail_start, n);
}